// round 16
// baseline (speedup 1.0000x reference)
#include <cuda_runtime.h>
#include <math.h>

#define SRC_LEN 400
#define TGT_LEN 100
#define Bsz     32
#define Ed      256
#define Hd      512
#define Vd      32000
#define G3H     1536
#define NB      128      // recurrence blocks (persistent)
#define TQ      4        // timesteps per logits block
#define TGROUPS (TGT_LEN / TQ)   // 25
#define LCH     512      // v per logits block
#define NCHB    63       // ceil(32000/512)
#define RTHR    512

// ---------------- device scratch --------------------------------------------
__device__ float  g_gi_enc[(size_t)SRC_LEN * G3H * Bsz];
__device__ float  g_gi_dec[(size_t)TGT_LEN * G3H * Bsz];
__device__ float2 g_h2[2][(Hd / 2) * Bsz];
__device__ float2 g_hall[(size_t)TGT_LEN * (Hd / 2) * Bsz];
__device__ float2 g_oeall[(size_t)TGT_LEN * (Ed / 2) * Bsz];
__device__ float  g_pm[(size_t)TGT_LEN * NCHB * Bsz];
__device__ float  g_ps[(size_t)TGT_LEN * NCHB * Bsz];
__device__ int    g_pi[(size_t)TGT_LEN * NCHB * Bsz];
__device__ float  g_loss_t[TGT_LEN];
__device__ unsigned g_flag[NB * 32];     // per-block epoch flag, 128B apart

// ---------------- f32x2 packed FMA ------------------------------------------
__device__ __forceinline__ float2 ffma2(float2 a, float2 b, float2 c) {
    unsigned long long A = *reinterpret_cast<unsigned long long*>(&a);
    unsigned long long B = *reinterpret_cast<unsigned long long*>(&b);
    unsigned long long C = *reinterpret_cast<unsigned long long*>(&c);
    unsigned long long D;
    asm("fma.rn.f32x2 %0, %1, %2, %3;" : "=l"(D) : "l"(A), "l"(B), "l"(C));
    return *reinterpret_cast<float2*>(&D);
}

__global__ void init_kernel() {
    int i = blockIdx.x * blockDim.x + threadIdx.x;
    if (i < Hd * Bsz) ((float*)g_h2[0])[i] = 0.0f;
    if (i < NB * 32) g_flag[i] = 0u;
}

// ---------------- gi precompute (fused enc+dec, 500 blocks) -------------------
__global__ void gi_fused(const int* __restrict__ src,
                         const int* __restrict__ tgt,
                         const float* __restrict__ emb,
                         const float* __restrict__ eWih,
                         const float* __restrict__ ebih,
                         const float* __restrict__ dWih,
                         const float* __restrict__ dbih) {
    __shared__ float2 xs2[(Ed / 2) * Bsz];
    __shared__ int    tk[Bsz];
    const int bid = blockIdx.x, tid = threadIdx.x;
    const int dec_mode = bid >= SRC_LEN;
    const int t = dec_mode ? bid - SRC_LEN : bid;
    const int* toks = dec_mode ? tgt : src;
    const float* Wih = dec_mode ? dWih : eWih;
    const float* bih = dec_mode ? dbih : ebih;

    if (tid < Bsz) {
        int tok;
        if (dec_mode) tok = (t == 0) ? 1 : toks[(t - 1) * Bsz + tid];
        else          tok = toks[t * Bsz + tid];
        tk[tid] = tok;
    }
    __syncthreads();
    {
        const int b = tid & 31, chunk = tid >> 5;
        const float* erow = emb + (size_t)tk[b] * Ed;
        #pragma unroll
        for (int c = 0; c < 8; c++) {
            int e0 = chunk * 32 + c * 4;
            float4 v = *(const float4*)(erow + e0);
            xs2[(e0 >> 1) * Bsz + b]       = make_float2(v.x, v.y);
            xs2[((e0 >> 1) + 1) * Bsz + b] = make_float2(v.z, v.w);
        }
    }
    __syncthreads();

    const int wid = tid >> 5, lane = tid & 31;
    float* out_t = (dec_mode ? g_gi_dec : g_gi_enc) + (size_t)t * G3H * Bsz;

    for (int jt = 0; jt < 24; jt++) {
        const int j0 = wid * 192 + jt * 8;
        float2 acc[8];
        #pragma unroll
        for (int i = 0; i < 8; i++) acc[i] = make_float2(0.f, 0.f);
        #pragma unroll 2
        for (int e = 0; e < Ed; e += 4) {
            const int e2 = e >> 1;
            float2 x01 = xs2[e2 * Bsz + lane];
            float2 x23 = xs2[(e2 + 1) * Bsz + lane];
            const float* wp = Wih + (size_t)j0 * Ed + e;
            #pragma unroll
            for (int jj = 0; jj < 8; jj++) {
                float4 w = *(const float4*)(wp + (size_t)jj * Ed);
                acc[jj] = ffma2(make_float2(w.x, w.y), x01, acc[jj]);
                acc[jj] = ffma2(make_float2(w.z, w.w), x23, acc[jj]);
            }
        }
        #pragma unroll
        for (int jj = 0; jj < 8; jj++)
            out_t[(size_t)(j0 + jj) * Bsz + lane] = acc[jj].x + acc[jj].y + bih[j0 + jj];
    }
}

// ---------------- warp-dataflow persistent GRU --------------------------------
// smem: ws[12][512] (24KB) + pp[2][16*3*32] (12KB) = 36KB
#define WS_F   0
#define PP_F   6144
#define PPSZ   (16 * 3 * 32)
#define REC_SMEM_BYTES ((6144 + 2 * PPSZ) * 4)

__device__ __forceinline__ void load_ws(float* ws, const float* __restrict__ Whh, int j0) {
    for (int i = threadIdx.x; i < 12 * 128; i += RTHR) {
        int r = i >> 7, k4 = i & 127;
        int g = r >> 2, jl = r & 3;
        ((float4*)ws)[r * 128 + k4] =
            *(const float4*)&Whh[((size_t)(g * Hd + j0 + jl)) * Hd + k4 * 4];
    }
}

// lane polls one producer flag of this warp's k-quarter (nanosleep backoff)
__device__ __forceinline__ void poll32(int kq, int lane, unsigned need) {
    const unsigned* p = &g_flag[(kq * 32 + lane) * 32];
    unsigned v;
    asm volatile("ld.acquire.gpu.global.u32 %0, [%1];" : "=r"(v) : "l"(p) : "memory");
    while (v < need) {
        asm volatile("nanosleep.u32 64;");
        asm volatile("ld.acquire.gpu.global.u32 %0, [%1];" : "=r"(v) : "l"(p) : "memory");
    }
}

// one step. hprev: [k/2][b] float2 global; hout viewed as floats (same layout).
__device__ __forceinline__ void df_step(const float* __restrict__ ws,
                                        const float2* __restrict__ hprev,
                                        const float* __restrict__ gi_t,
                                        const float* bb,        // 3 biases (kq0)
                                        float* __restrict__ hout_f,
                                        float* __restrict__ ppb,
                                        int j0, unsigned epoch, float& hold) {
    const int tid = threadIdx.x, wid = tid >> 5, lane = tid & 31;
    const int jo = wid & 3, kq = wid >> 2;
    const int j = j0 + jo;
    float* pp = ppb + (epoch & 1u) * PPSZ;

    // gate-input prefetch (kq0 only) — issued before poll, lands during k-loop
    float pg0 = 0.f, pg1 = 0.f, pg2 = 0.f;
    if (kq == 0) {
        pg0 = __ldcg(&gi_t[(size_t)(0 * Hd + j) * Bsz + lane]);
        pg1 = __ldcg(&gi_t[(size_t)(1 * Hd + j) * Bsz + lane]);
        pg2 = __ldcg(&gi_t[(size_t)(2 * Hd + j) * Bsz + lane]);
    }

    poll32(kq, lane, epoch - 1u);
    __syncwarp();

    float2 a0 = make_float2(0.f, 0.f), a1 = a0, a2 = a0;
    const float* w0 = ws + (0 * 4 + jo) * Hd;
    const float* w1 = ws + (1 * 4 + jo) * Hd;
    const float* w2 = ws + (2 * 4 + jo) * Hd;
    const int rbeg = kq * 64;
    #pragma unroll 8
    for (int r = rbeg; r < rbeg + 64; r += 2) {
        float2 x0 = __ldcg(&hprev[r * Bsz + lane]);
        float2 x1 = __ldcg(&hprev[(r + 1) * Bsz + lane]);
        const int k = 2 * r;
        float4 wa = *(const float4*)(w0 + k);
        float4 wb = *(const float4*)(w1 + k);
        float4 wc = *(const float4*)(w2 + k);
        a0 = ffma2(make_float2(wa.x, wa.y), x0, a0);
        a0 = ffma2(make_float2(wa.z, wa.w), x1, a0);
        a1 = ffma2(make_float2(wb.x, wb.y), x0, a1);
        a1 = ffma2(make_float2(wb.z, wb.w), x1, a1);
        a2 = ffma2(make_float2(wc.x, wc.y), x0, a2);
        a2 = ffma2(make_float2(wc.z, wc.w), x1, a2);
    }
    pp[(wid * 3 + 0) * 32 + lane] = a0.x + a0.y;
    pp[(wid * 3 + 1) * 32 + lane] = a1.x + a1.y;
    pp[(wid * 3 + 2) * 32 + lane] = a2.x + a2.y;

    // j-group barrier: warps {jo, jo+4, jo+8, jo+12} (128 threads)
    asm volatile("bar.sync %0, 128;" :: "r"(1 + jo) : "memory");

    if (kq == 0) {
        float s0 = 0.f, s1 = 0.f, s2 = 0.f;
        #pragma unroll
        for (int q = 0; q < 4; q++) {
            const int w = q * 4 + jo;
            s0 += pp[(w * 3 + 0) * 32 + lane];
            s1 += pp[(w * 3 + 1) * 32 + lane];
            s2 += pp[(w * 3 + 2) * 32 + lane];
        }
        float r = 1.0f / (1.0f + expf(-(pg0 + s0 + bb[0])));
        float z = 1.0f / (1.0f + expf(-(pg1 + s1 + bb[1])));
        float n = tanhf(pg2 + r * (s2 + bb[2]));     // FIX: reset gate applied
        float hn = (1.0f - z) * n + z * hold;
        hold = hn;
        __stcg(&hout_f[(j >> 1) * 64 + 2 * lane + (j & 1)], hn);
        asm volatile("bar.sync 7, 128;" ::: "memory");      // 4 kq0 warps
        if (tid == 0)
            asm volatile("st.release.gpu.global.u32 [%0], %1;"
                         :: "l"(&g_flag[blockIdx.x * 32]), "r"(epoch) : "memory");
    }
}

__global__ void __launch_bounds__(RTHR, 1)
rec_persist(const float* __restrict__ eWhh, const float* __restrict__ ebhh,
            const float* __restrict__ dWhh, const float* __restrict__ dbhh) {
    extern __shared__ float sm[];
    float* ws  = sm + WS_F;
    float* ppb = sm + PP_F;
    const int tid = threadIdx.x, wid = tid >> 5, lane = tid & 31;
    const int jo = wid & 3, kq = wid >> 2;
    const int j0 = blockIdx.x * 4, j = j0 + jo;

    load_ws(ws, eWhh, j0);
    float bb[3] = {0.f, 0.f, 0.f};
    if (kq == 0) {
        bb[0] = __ldg(&ebhh[j]);
        bb[1] = __ldg(&ebhh[Hd + j]);
        bb[2] = __ldg(&ebhh[2 * Hd + j]);
    }
    __syncthreads();

    float hold = 0.f;                       // h0 = 0; warp owns j thereafter
    unsigned epoch = 1;
    for (int t = 0; t < SRC_LEN; t++, epoch++) {
        df_step(ws, g_h2[t & 1], g_gi_enc + (size_t)t * G3H * Bsz, bb,
                (float*)g_h2[(t & 1) ^ 1], ppb, j0, epoch, hold);
    }
    // encoder final h in g_h2[0]; hold = h[399][j][lane]

    __syncthreads();
    load_ws(ws, dWhh, j0);
    if (kq == 0) {
        bb[0] = __ldg(&dbhh[j]);
        bb[1] = __ldg(&dbhh[Hd + j]);
        bb[2] = __ldg(&dbhh[2 * Hd + j]);
    }
    __syncthreads();

    for (int t = 0; t < TGT_LEN; t++, epoch++) {
        const float2* hprev = (t == 0) ? g_h2[0]
                                       : &g_hall[(size_t)(t - 1) * (Hd / 2) * Bsz];
        df_step(ws, hprev, g_gi_dec + (size_t)t * G3H * Bsz, bb,
                (float*)&g_hall[(size_t)t * (Hd / 2) * Bsz], ppb, j0, epoch, hold);
    }
}

// ---------------- decoder phase B: batched pre, 4 e-quarters per t ------------
__global__ void __launch_bounds__(256)
pre_all(const float* __restrict__ preW, const float* __restrict__ preb) {
    extern __shared__ float sm[];
    float2* hs = (float2*)sm;
    const int t = blockIdx.x >> 2, q = blockIdx.x & 3;
    const int tid = threadIdx.x;
    {
        const float4* s4 = (const float4*)&g_hall[(size_t)t * (Hd / 2) * Bsz];
        float4* d4 = (float4*)hs;
        for (int i = tid; i < (Hd * Bsz) / 4; i += 256) d4[i] = __ldg(s4 + i);
        __syncthreads();
    }
    const int wid = tid >> 5, lane = tid & 31;
    const int e0 = q * 64 + wid * 8;
    float2 acc[8];
    #pragma unroll
    for (int i = 0; i < 8; i++) acc[i] = make_float2(0.f, 0.f);
    const float* wp = preW + (size_t)e0 * Hd;
    #pragma unroll 2
    for (int k = 0; k < Hd; k += 4) {
        const int k2 = k >> 1;
        float2 x01 = hs[k2 * Bsz + lane];
        float2 x23 = hs[(k2 + 1) * Bsz + lane];
        #pragma unroll
        for (int r = 0; r < 8; r++) {
            float4 w = *(const float4*)(wp + (size_t)r * Hd + k);
            acc[r] = ffma2(make_float2(w.x, w.y), x01, acc[r]);
            acc[r] = ffma2(make_float2(w.z, w.w), x23, acc[r]);
        }
    }
    #pragma unroll
    for (int i = 0; i < 4; i++) {
        float v0 = acc[2 * i].x     + acc[2 * i].y     + preb[e0 + 2 * i];
        float v1 = acc[2 * i + 1].x + acc[2 * i + 1].y + preb[e0 + 2 * i + 1];
        g_oeall[((size_t)t * (Ed / 2) + (e0 >> 1) + i) * Bsz + lane] =
            make_float2(v0, v1);
    }
}

// ---------------- decoder phase C: batched logits, 512 thr, 512-v chunks ------
#define LG_SMEM_F (4 * (Ed / 2) * Bsz * 2 + 3 * (TQ * 16 * 32))
__global__ void __launch_bounds__(512, 1)
logits_all(const float* __restrict__ emb, const float* __restrict__ outb) {
    extern __shared__ float sm[];
    float2* oes = (float2*)sm;
    float*  mm  = sm + 4 * (Ed / 2) * Bsz * 2;
    float*  ms  = mm + TQ * 16 * 32;
    int*    mi  = (int*)(ms + TQ * 16 * 32);

    const int bid = blockIdx.x;
    const int c = bid / TGROUPS, grp = bid % TGROUPS;
    const int t0 = grp * TQ;
    const int tid = threadIdx.x, wid = tid >> 5, lane = tid & 31;

    {
        const float4* s4 = (const float4*)&g_oeall[(size_t)t0 * (Ed / 2) * Bsz];
        float4* d4 = (float4*)oes;
        for (int i = tid; i < 4 * (Ed * Bsz) / 4; i += 512) d4[i] = __ldg(s4 + i);
        __syncthreads();
    }

    const int base = c * LCH + wid * 32;
    float m[TQ], s[TQ]; int bi[TQ];
    #pragma unroll
    for (int t = 0; t < TQ; t++) { m[t] = -INFINITY; s[t] = 0.f; bi[t] = 0; }

    for (int vt = 0; vt < 4; vt++) {
        const int vb = base + vt * 8;
        if (vb >= Vd) break;
        float2 acc[TQ][8];
        #pragma unroll
        for (int t = 0; t < TQ; t++)
            #pragma unroll
            for (int i = 0; i < 8; i++) acc[t][i] = make_float2(0.f, 0.f);
        const float* ep = emb + (size_t)vb * Ed;

        for (int e = 0; e < Ed; e += 4) {
            const int e2 = e >> 1;
            float2 x01[TQ], x23[TQ];
            #pragma unroll
            for (int t = 0; t < TQ; t++) {
                x01[t] = oes[t * (Ed / 2) * Bsz + e2 * Bsz + lane];
                x23[t] = oes[t * (Ed / 2) * Bsz + (e2 + 1) * Bsz + lane];
            }
            #pragma unroll
            for (int vv = 0; vv < 8; vv++) {
                float4 w = *(const float4*)(ep + (size_t)vv * Ed + e);
                float2 w01 = make_float2(w.x, w.y), w23 = make_float2(w.z, w.w);
                #pragma unroll
                for (int t = 0; t < TQ; t++) {
                    acc[t][vv] = ffma2(w01, x01[t], acc[t][vv]);
                    acc[t][vv] = ffma2(w23, x23[t], acc[t][vv]);
                }
            }
        }
        #pragma unroll
        for (int vv = 0; vv < 8; vv++) {
            float lb = outb[vb + vv];
            #pragma unroll
            for (int t = 0; t < TQ; t++) {
                float l = acc[t][vv].x + acc[t][vv].y + lb;
                if (l > m[t]) { s[t] = s[t] * __expf(m[t] - l) + 1.0f; m[t] = l; bi[t] = vb + vv; }
                else          { s[t] += __expf(l - m[t]); }
            }
        }
    }
    #pragma unroll
    for (int t = 0; t < TQ; t++) {
        mm[(t * 16 + wid) * 32 + lane] = m[t];
        ms[(t * 16 + wid) * 32 + lane] = s[t];
        mi[(t * 16 + wid) * 32 + lane] = bi[t];
    }
    __syncthreads();

    if (wid < TQ) {
        const int tt = wid;
        float M = mm[(tt * 16 + 0) * 32 + lane];
        float S = ms[(tt * 16 + 0) * 32 + lane];
        int   I = mi[(tt * 16 + 0) * 32 + lane];
        #pragma unroll
        for (int w = 1; w < 16; w++) {
            float m2 = mm[(tt * 16 + w) * 32 + lane];
            float s2 = ms[(tt * 16 + w) * 32 + lane];
            int   i2 = mi[(tt * 16 + w) * 32 + lane];
            if (m2 > M) { S = S * __expf(M - m2) + s2; I = i2; M = m2; }
            else        { S += s2 * __expf(m2 - M); }
        }
        const size_t idx = ((size_t)(t0 + tt) * NCHB + c) * 32 + lane;
        g_pm[idx] = M; g_ps[idx] = S; g_pi[idx] = I;
    }
}

// ---------------- decoder phase D: per-t merge, tokens, loss ------------------
__global__ void __launch_bounds__(256)
merge_all(const int* __restrict__ tgt, const float* __restrict__ emb,
          const float* __restrict__ outb, float* __restrict__ dout) {
    __shared__ float smm[8 * 32], sms[8 * 32];
    __shared__ int   smi[8 * 32];
    const int t = blockIdx.x, tid = threadIdx.x, b = tid & 31, cg = tid >> 5;

    float m = -INFINITY, s = 0.f; int bi = 0;
    const int cb = cg * 8, ce = (cb + 8 < NCHB) ? cb + 8 : NCHB;
    for (int c = cb; c < ce; c++) {
        const size_t idx = ((size_t)t * NCHB + c) * 32 + b;
        float m2 = g_pm[idx], s2 = g_ps[idx];
        int   i2 = g_pi[idx];
        if (m2 > m) { s = s * __expf(m - m2) + s2; bi = i2; m = m2; }
        else        { s += s2 * __expf(m2 - m); }
    }
    smm[cg * 32 + b] = m; sms[cg * 32 + b] = s; smi[cg * 32 + b] = bi;
    __syncthreads();

    if (tid < 32) {
        m = smm[tid]; s = sms[tid]; bi = smi[tid];
        #pragma unroll
        for (int c2 = 1; c2 < 8; c2++) {
            float m2 = smm[c2 * 32 + tid];
            float s2 = sms[c2 * 32 + tid];
            int   i2 = smi[c2 * 32 + tid];
            if (m2 > m) { s = s * __expf(m - m2) + s2; bi = i2; m = m2; }
            else        { s += s2 * __expf(m2 - m); }
        }
        int gold = tgt[t * Bsz + tid];
        float2 acc = make_float2(0.f, 0.f);
        const float* grow = emb + (size_t)gold * Ed;
        #pragma unroll 4
        for (int e = 0; e < Ed; e += 4) {
            float4 w = *(const float4*)(grow + e);
            float2 o01 = g_oeall[((size_t)t * (Ed / 2) + (e >> 1)) * Bsz + tid];
            float2 o23 = g_oeall[((size_t)t * (Ed / 2) + (e >> 1) + 1) * Bsz + tid];
            acc = ffma2(make_float2(w.x, w.y), o01, acc);
            acc = ffma2(make_float2(w.z, w.w), o23, acc);
        }
        float lg = acc.x + acc.y + outb[gold];
        float prob = expf(lg - m) / s;
        float nll = -logf(prob + 1e-20f);
        float maskf = (gold != 0) ? 1.0f : 0.0f;
        float num = nll * maskf, den = maskf;
        #pragma unroll
        for (int o = 16; o > 0; o >>= 1) {
            num += __shfl_down_sync(0xffffffffu, num, o);
            den += __shfl_down_sync(0xffffffffu, den, o);
        }
        dout[t * Bsz + tid] = (float)bi;
        if (tid == 0) g_loss_t[t] = num / fmaxf(den, 1.0f);
    }
}

__global__ void loss_fin(float* __restrict__ dout, int out_size) {
    if (out_size <= TGT_LEN * Bsz) return;
    const int lane = threadIdx.x;
    float s = 0.f;
    for (int t = lane; t < TGT_LEN; t += 32) s += g_loss_t[t];
    #pragma unroll
    for (int o = 16; o > 0; o >>= 1) s += __shfl_down_sync(0xffffffffu, s, o);
    if (lane == 0) dout[TGT_LEN * Bsz] = s;
}

// ---------------- launch ------------------------------------------------------
extern "C" void kernel_launch(void* const* d_in, const int* in_sizes, int n_in,
                              void* d_out, int out_size) {
    const int*   src  = (const int*)  d_in[0];
    const int*   tgt  = (const int*)  d_in[1];
    const float* emb  = (const float*)d_in[2];
    const float* eWih = (const float*)d_in[3];
    const float* eWhh = (const float*)d_in[4];
    const float* ebih = (const float*)d_in[5];
    const float* ebhh = (const float*)d_in[6];
    const float* dWih = (const float*)d_in[7];
    const float* dWhh = (const float*)d_in[8];
    const float* dbih = (const float*)d_in[9];
    const float* dbhh = (const float*)d_in[10];
    const float* preW = (const float*)d_in[11];
    const float* preb = (const float*)d_in[12];
    const float* outb = (const float*)d_in[13];
    float* out = (float*)d_out;

    static int attr_done = 0;
    if (!attr_done) {
        cudaFuncSetAttribute(rec_persist, cudaFuncAttributeMaxDynamicSharedMemorySize,
                             REC_SMEM_BYTES);
        cudaFuncSetAttribute(pre_all, cudaFuncAttributeMaxDynamicSharedMemorySize,
                             65536);
        cudaFuncSetAttribute(logits_all, cudaFuncAttributeMaxDynamicSharedMemorySize,
                             LG_SMEM_F * 4);
        attr_done = 1;
    }

    init_kernel<<<64, 256>>>();
    gi_fused<<<SRC_LEN + TGT_LEN, 256>>>(src, tgt, emb, eWih, ebih, dWih, dbih);
    rec_persist<<<NB, RTHR, REC_SMEM_BYTES>>>(eWhh, ebhh, dWhh, dbhh);
    pre_all<<<TGT_LEN * 4, 256, 65536>>>(preW, preb);
    logits_all<<<NCHB * TGROUPS, 512, LG_SMEM_F * 4>>>(emb, outb);
    merge_all<<<TGT_LEN, 256>>>(tgt, emb, outb, out);
    loss_fin<<<1, 32>>>(out, out_size);
}